// round 13
// baseline (speedup 1.0000x reference)
#include <cuda_runtime.h>
#include <cuda_bf16.h>
#include <cuda_fp16.h>
#include <cstdint>

#define NSPK 2048
#define MUTT 16
#define DDIM 512
#define NROWS (NSPK*MUTT)
#define EPSC 1e-6f
#define LOG2E 1.4426950408889634f

// ---- k2 tiling: 64 rows x 512 cols per tile, 128 threads (4 warps, 32x64 each) ----
#define MTR 64
#define NCH_CTA 4               // 4 col-chunks of 128
#define NSLICE (NCH_CTA*4)      // 16 B-slices of 16KB
#define A_SLICE 8192            // 64 rows x 128 bytes per K128-slice
#define SLICE_B 16384
#define OFF_B   32768           // A resident: 4 x 8KB
#define SMEM_K2 (OFF_B + 2*SLICE_B)   // 65536 -> 3 CTAs/SM, ~168 regs/thread
#define NRB (NROWS/MTR)         // 512 row blocks
#define NTILES (NRB*4)          // 2048
#define NPERS 444               // 3 x 148 persistent CTAs
#define ASTR ((size_t)NROWS*128)
#define BSTR ((size_t)NSPK*128)

// ---- scratch: K-slice-major, pre-swizzled for ldsm ----
__device__ __align__(256) uint8_t g_A8s[4*NROWS*128];
__device__ __align__(256) uint8_t g_B8s[4*NSPK*128];
__device__ float g_rowsum[NROWS];
__device__ float g_cosF[NROWS];
__device__ float g_cosL[NROWS];
__device__ unsigned g_count[NRB];
__device__ unsigned g_work;

// ---------------- helpers ----------------
__device__ __forceinline__ uint32_t smem_u32(const void* p) {
    uint32_t a;
    asm("{ .reg .u64 t; cvta.to.shared.u64 t, %1; cvt.u32.u64 %0, t; }" : "=r"(a) : "l"(p));
    return a;
}
__device__ __forceinline__ void mbar_init(uint32_t a, uint32_t c) {
    asm volatile("mbarrier.init.shared.b64 [%0], %1;" :: "r"(a), "r"(c) : "memory");
}
__device__ __forceinline__ void mbar_expect(uint32_t a, uint32_t tx) {
    asm volatile("mbarrier.arrive.expect_tx.shared.b64 _, [%0], %1;" :: "r"(a), "r"(tx) : "memory");
}
__device__ __forceinline__ void mbar_wait(uint32_t a, uint32_t par) {
    asm volatile(
        "{\n\t.reg .pred P;\n\t"
        "LW%=:\n\t"
        "mbarrier.try_wait.parity.acquire.cta.shared::cta.b64 P, [%0], %1, 0x989680;\n\t"
        "@P bra LD%=;\n\t"
        "bra LW%=;\n\t"
        "LD%=:\n\t}"
        :: "r"(a), "r"(par) : "memory");
}
__device__ __forceinline__ void bulk_g2s(uint32_t dst, const void* src, uint32_t bytes, uint32_t mbar) {
    asm volatile("cp.async.bulk.shared::cluster.global.mbarrier::complete_tx::bytes [%0], [%1], %2, [%3];"
                 :: "r"(dst), "l"(src), "r"(bytes), "r"(mbar) : "memory");
}
__device__ __forceinline__ void ldsm4(uint32_t r[4], uint32_t addr) {
    asm volatile("ldmatrix.sync.aligned.m8n8.x4.shared.b16 {%0,%1,%2,%3}, [%4];"
                 : "=r"(r[0]), "=r"(r[1]), "=r"(r[2]), "=r"(r[3]) : "r"(addr));
}
__device__ __forceinline__ void mma_e4m3_h(uint32_t c[2], const uint32_t a[4], const uint32_t b[2]) {
    asm volatile("mma.sync.aligned.m16n8k32.row.col.f16.e4m3.e4m3.f16 "
                 "{%0,%1}, {%2,%3,%4,%5}, {%6,%7}, {%0,%1};"
                 : "+r"(c[0]), "+r"(c[1])
                 : "r"(a[0]), "r"(a[1]), "r"(a[2]), "r"(a[3]), "r"(b[0]), "r"(b[1]));
}
__device__ __forceinline__ float ex2f(float x) {
    float y; asm("ex2.approx.ftz.f32 %0, %1;" : "=f"(y) : "f"(x)); return y;
}
__device__ __forceinline__ __half2 ex2_h2(__half2 x) {
    __half2 y;
    asm("ex2.approx.f16x2 %0, %1;" : "=r"(*(uint32_t*)&y) : "r"(*(const uint32_t*)&x));
    return y;
}
__device__ __forceinline__ uint32_t pack4_e4m3(float v0, float v1, float v2, float v3) {
    uint16_t lo, hi;
    asm("cvt.rn.satfinite.e4m3x2.f32 %0, %1, %2;" : "=h"(lo) : "f"(v1), "f"(v0));
    asm("cvt.rn.satfinite.e4m3x2.f32 %0, %1, %2;" : "=h"(hi) : "f"(v3), "f"(v2));
    return (uint32_t)lo | ((uint32_t)hi << 16);
}

// ---------------- K1: per-speaker prep -> slice-major pre-swizzled fp8 ----------------
__global__ __launch_bounds__(128) void k1_prep(const float* __restrict__ dvecs,
                                               const float* __restrict__ wp,
                                               float* out) {
    __shared__ float2 sde[MUTT*128];
    __shared__ float  sfe[MUTT];
    __shared__ float  red[4];

    const int j = blockIdx.x, tid = threadIdx.x;
    const int lane = tid & 31, wid = tid >> 5;
    const float w = *wp;
    const float sA = sqrtf(w * LOG2E);

    if (j == 0 && tid == 0) { out[0] = 0.f; g_work = 0u; }
    if (tid < MUTT) g_rowsum[j*MUTT + tid] = 0.f;
    if (j < NRB && tid == 64) g_count[j] = 0u;

    const int ss = tid >> 5, kc = (tid >> 2) & 7, wd = tid & 3;

    const float4* src = (const float4*)(dvecs + (size_t)j * MUTT * DDIM);
    float4 v[MUTT];
    #pragma unroll
    for (int i = 0; i < MUTT; i++) v[i] = src[i*128 + tid];

    float4 s = make_float4(0.f, 0.f, 0.f, 0.f);
    #pragma unroll
    for (int i = 0; i < MUTT; i++) { s.x += v[i].x; s.y += v[i].y; s.z += v[i].z; s.w += v[i].w; }

    float ssqp = s.x*s.x + s.y*s.y + s.z*s.z + s.w*s.w;
    #pragma unroll
    for (int o = 16; o; o >>= 1) ssqp += __shfl_xor_sync(0xffffffffu, ssqp, o);
    if (lane == 0) red[wid] = ssqp;

    #pragma unroll
    for (int i = 0; i < MUTT; i++) {
        const float dp = v[i].x*s.x + v[i].y*s.y + v[i].z*s.z + v[i].w*s.w;
        const float ep = v[i].x*v[i].x + v[i].y*v[i].y + v[i].z*v[i].z + v[i].w*v[i].w;
        sde[i*128 + tid] = make_float2(dp, ep);
    }
    __syncthreads();

    const float ssq = red[0] + red[1] + red[2] + red[3];
    const float inv_S = rsqrtf(ssq);
    const float fB = inv_S * sA;
    {
        const uint32_t off = (uint32_t)(((kc*16) ^ ((j & 7) << 4)) + wd*4);
        *(uint32_t*)(g_B8s + (size_t)ss*BSTR + (size_t)j*128 + off) =
            pack4_e4m3(s.x*fB, s.y*fB, s.z*fB, s.w*fB);
    }

    #pragma unroll
    for (int q = 0; q < 4; q++) {
        const int i = wid + 4*q;
        float2 a0 = sde[i*128 + lane];
        const float2 a1 = sde[i*128 + lane + 32];
        const float2 a2 = sde[i*128 + lane + 64];
        const float2 a3 = sde[i*128 + lane + 96];
        float dp = a0.x + a1.x + a2.x + a3.x;
        float ep = a0.y + a1.y + a2.y + a3.y;
        #pragma unroll
        for (int o = 16; o; o >>= 1) {
            dp += __shfl_xor_sync(0xffffffffu, dp, o);
            ep += __shfl_xor_sync(0xffffffffu, ep, o);
        }
        if (lane == 0) {
            const float inv_e = rsqrtf(ep);
            const int r = j * MUTT + i;
            const float cosF = dp * inv_e * inv_S;
            const float den  = fmaxf(ssq - 2.f*dp + ep, 1e-20f);
            const float cosL = (dp - ep) * inv_e * rsqrtf(den);
            g_cosF[r] = fmaxf(cosF, EPSC);
            g_cosL[r] = fmaxf(cosL, EPSC);
            sfe[i] = inv_e * sA;
        }
    }
    __syncthreads();

    #pragma unroll
    for (int i = 0; i < MUTT; i++) {
        const float fe = sfe[i];
        const int r = j*MUTT + i;
        const uint32_t off = (uint32_t)(((kc*16) ^ ((r & 7) << 4)) + wd*4);
        *(uint32_t*)(g_A8s + (size_t)ss*ASTR + (size_t)r*128 + off) =
            pack4_e4m3(v[i].x*fe, v[i].y*fe, v[i].z*fe, v[i].w*fe);
    }
}

// ---------------- K2: persistent TMA-fed fp8 GEMM + exp row-sum + fused loss ----------------
// grid = 444 persistent CTAs; tile t: rowBlock = t>>2 (64 rows), colQ = t&3 (512 cols)
__global__ __launch_bounds__(128, 3) void k2_gemm(const float* __restrict__ wp, float* out) {
    extern __shared__ unsigned char dyns[];
    __shared__ __align__(8) uint64_t mbar[3];   // [0,1]: B double buffer, [2]: A
    __shared__ float rowAcc[MTR];
    __shared__ float red[4];
    __shared__ unsigned sh_next;
    __shared__ int s_last;
    const uint32_t sb = smem_u32(dyns);
    const uint32_t mb = smem_u32(mbar);

    const int tid = threadIdx.x;
    const int lane = tid & 31;
    const int warp = tid >> 5;
    const int wm = warp >> 1;     // 0..1: 32 rows
    const int wn = warp & 1;      // 0..1: 64 cols
    const float w = *wp;
    const float K = w * LOG2E;
    const __half2 cKh = __float2half2_rn(K * EPSC);

    if (tid == 0) {
        #pragma unroll
        for (int i = 0; i < 3; i++) mbar_init(mb + i*8, 1);
        sh_next = atomicAdd(&g_work, 1u);
    }
    __syncthreads();

    unsigned t = sh_next;
    if (t >= NTILES) return;

    // ---- ldsm lane addresses (row/col-local; bases updated per tile via rowBase offsets) ----
    const int grp = lane >> 3, wi = lane & 7;
    uint32_t aBase[2], aMask[2];
    const uint32_t aB16 = (uint32_t)((grp >> 1) * 16);
    #pragma unroll
    for (int mt = 0; mt < 2; mt++) {
        const int row = wm*32 + mt*16 + (grp & 1)*8 + wi;
        aBase[mt] = sb + (uint32_t)(row * 128);
        aMask[mt] = (uint32_t)((row & 7) << 4);
    }
    uint32_t bBase[4], bMask[4];
    const uint32_t bB16 = (uint32_t)((grp & 1) * 16);
    #pragma unroll
    for (int p = 0; p < 4; p++) {
        const int n = wn*64 + p*16 + (grp >> 1)*8 + wi;
        bBase[p] = sb + OFF_B + (uint32_t)(n * 128);
        bMask[p] = (uint32_t)((n & 7) << 4);
    }

    // ---- prologue: A(t) + B0(t) ----
    int rowBase = (int)(t >> 2) * MTR;
    int colBase = (int)(t & 3) * NCH_CTA;
    if (tid == 0) {
        mbar_expect(mb + 16, 4*A_SLICE);
        #pragma unroll
        for (int ss = 0; ss < 4; ss++)
            bulk_g2s(sb + (uint32_t)(ss*A_SLICE), g_A8s + (size_t)ss*ASTR + (size_t)rowBase*128,
                     A_SLICE, mb + 16);
        mbar_expect(mb + 0, 16384);
        bulk_g2s(sb + OFF_B, g_B8s + (size_t)colBase*16384, 16384u, mb + 0);
    }
    int aPar = 0;

    while (true) {
        const int rowBlock = rowBase / MTR;
        mbar_wait(mb + 16, aPar);
        aPar ^= 1;

        float rs[4];
        #pragma unroll
        for (int k = 0; k < 4; k++) rs[k] = 0.f;

        for (int c8 = 0; c8 < NCH_CTA; c8++) {
            uint32_t acc[2][8][2];
            #pragma unroll
            for (int x = 0; x < 2; x++)
                #pragma unroll
                for (int y = 0; y < 8; y++) { acc[x][y][0] = 0u; acc[x][y][1] = 0u; }

            #pragma unroll
            for (int sc = 0; sc < 4; sc++) {
                const int s = c8*4 + sc;
                const int bfi = s & 1;
                mbar_wait(mb + bfi*8, (s >> 1) & 1);
                __syncthreads();   // buffer (s+1)&1 fully consumed (read at s-1)
                if (tid == 0 && s + 1 < NSLICE) {
                    const int pb = (s + 1) & 1;
                    const int nc = colBase + ((s + 1) >> 2), ksl = (s + 1) & 3;
                    mbar_expect(mb + pb*8, 16384);
                    bulk_g2s(sb + OFF_B + (uint32_t)(pb*16384),
                             g_B8s + (size_t)ksl*BSTR + (size_t)nc*16384, 16384u, mb + pb*8);
                }

                const uint32_t aSl = (uint32_t)(sc * A_SLICE);
                const uint32_t bBuf = (uint32_t)(bfi * SLICE_B);
                #pragma unroll
                for (int kk = 0; kk < 4; kk++) {
                    uint32_t afr[2][4];
                    #pragma unroll
                    for (int mt = 0; mt < 2; mt++)
                        ldsm4(afr[mt], aBase[mt] + aSl + (((uint32_t)(kk*32) | aB16) ^ aMask[mt]));
                    uint32_t bfr[8][2];
                    #pragma unroll
                    for (int p = 0; p < 4; p++) {
                        uint32_t tr[4];
                        ldsm4(tr, bBase[p] + bBuf + (((uint32_t)(kk*32) | bB16) ^ bMask[p]));
                        bfr[2*p][0] = tr[0]; bfr[2*p][1] = tr[1];
                        bfr[2*p+1][0] = tr[2]; bfr[2*p+1][1] = tr[3];
                    }
                    #pragma unroll
                    for (int mt = 0; mt < 2; mt++)
                        #pragma unroll
                        for (int nt = 0; nt < 8; nt++)
                            mma_e4m3_h(acc[mt][nt], afr[mt], bfr[nt]);
                }
            }

            // per-chunk epilogue: f16 exp-sums across nt
            #pragma unroll
            for (int mt = 0; mt < 2; mt++) {
                __half2 h0 = ex2_h2(__hmax2(*(__half2*)&acc[mt][0][0], cKh));
                __half2 h1 = ex2_h2(__hmax2(*(__half2*)&acc[mt][0][1], cKh));
                #pragma unroll
                for (int nt = 1; nt < 8; nt++) {
                    h0 = __hadd2(h0, ex2_h2(__hmax2(*(__half2*)&acc[mt][nt][0], cKh)));
                    h1 = __hadd2(h1, ex2_h2(__hmax2(*(__half2*)&acc[mt][nt][1], cKh)));
                }
                const float2 f0 = __half22float2(h0);
                const float2 f1 = __half22float2(h1);
                rs[mt*2]   += f0.x + f0.y;
                rs[mt*2+1] += f1.x + f1.y;
            }
        }

        // ---- tile done: all ldsm complete after this barrier; pop + prefetch next tile ----
        if (tid == 0) sh_next = atomicAdd(&g_work, 1u);
        __syncthreads();
        const unsigned nxt = sh_next;
        if (tid == 0 && nxt < NTILES) {
            const int nrb = (int)(nxt >> 2) * MTR;
            const int ncb = (int)(nxt & 3) * NCH_CTA;
            mbar_expect(mb + 16, 4*A_SLICE);
            #pragma unroll
            for (int ss = 0; ss < 4; ss++)
                bulk_g2s(sb + (uint32_t)(ss*A_SLICE), g_A8s + (size_t)ss*ASTR + (size_t)nrb*128,
                         A_SLICE, mb + 16);
            mbar_expect(mb + 0, 16384);
            bulk_g2s(sb + OFF_B, g_B8s + (size_t)ncb*16384, 16384u, mb + 0);
        }

        // ---- row reduction (dedicated smem; overlaps the in-flight TMAs) ----
        if (tid < MTR) rowAcc[tid] = 0.f;
        __syncthreads();
        const int g8 = lane >> 2, tt = lane & 3;
        #pragma unroll
        for (int k = 0; k < 4; k++) {
            float v = rs[k];
            v += __shfl_xor_sync(0xffffffffu, v, 1);
            v += __shfl_xor_sync(0xffffffffu, v, 2);
            if (tt == 0)
                atomicAdd(&rowAcc[wm*32 + (k >> 1)*16 + (k & 1)*8 + g8], v);
        }
        __syncthreads();

        if (tid < MTR) atomicAdd(&g_rowsum[rowBase + tid], rowAcc[tid]);
        __threadfence();
        if (tid == 0) {
            const unsigned o = atomicAdd(&g_count[rowBlock], 1u);
            s_last = (o == 3u);
        }
        __syncthreads();

        if (s_last) {
            __threadfence();
            float v = 0.f;
            if (tid < MTR) {
                const int r = rowBase + tid;
                const float fF = g_cosF[r], fL = g_cosL[r];
                v = __logf(g_rowsum[r] - ex2f(K * fF) + ex2f(K * fL)) - w * fL;
            }
            #pragma unroll
            for (int o = 16; o; o >>= 1) v += __shfl_xor_sync(0xffffffffu, v, o);
            if (lane == 0) red[warp] = v;
            __syncthreads();
            if (tid == 0) atomicAdd(out, red[0] + red[1] + red[2] + red[3]);
        }

        if (nxt >= NTILES) break;
        rowBase = (int)(nxt >> 2) * MTR;
        colBase = (int)(nxt & 3) * NCH_CTA;
    }
}

// ---------------- launcher ----------------
extern "C" void kernel_launch(void* const* d_in, const int* in_sizes, int n_in,
                              void* d_out, int out_size) {
    const float* dvecs = (const float*)d_in[0];
    const float* wp    = (const float*)d_in[1];
    float* out = (float*)d_out;

    cudaFuncSetAttribute(k2_gemm, cudaFuncAttributeMaxDynamicSharedMemorySize, SMEM_K2);

    k1_prep<<<NSPK, 128>>>(dvecs, wp, out);
    k2_gemm<<<NPERS, 128, SMEM_K2>>>(wp, out);
}

// round 14
// speedup vs baseline: 1.1050x; 1.1050x over previous
#include <cuda_runtime.h>
#include <cuda_bf16.h>
#include <cuda_fp16.h>
#include <cstdint>

#define NSPK 2048
#define MUTT 16
#define DDIM 512
#define NROWS (NSPK*MUTT)
#define EPSC 1e-6f
#define LOG2E 1.4426950408889634f

// ---- k2 tiling: 64 rows x 512 cols per CTA, 128 threads (4 warps, 32x64 each) ----
#define MTR 64
#define NCH_CTA 4               // 4 col-chunks of 128
#define NSLICE (NCH_CTA*4)      // 16 B-slices of 16KB
#define A_SLICE 8192            // 64 rows x 128 bytes per K128-slice
#define SLICE_B 16384
#define OFF_B   32768           // A resident: 4 x 8KB
#define SMEM_K2 (OFF_B + 2*SLICE_B + 512)   // 66048 -> 3 CTAs/SM, ~168 regs/thread
#define NRB (NROWS/MTR)         // 512 row blocks
#define ASTR ((size_t)NROWS*128)
#define BSTR ((size_t)NSPK*128)

// ---- scratch: K-slice-major, pre-swizzled for ldsm ----
__device__ __align__(256) uint8_t g_A8s[4*NROWS*128];
__device__ __align__(256) uint8_t g_B8s[4*NSPK*128];
__device__ float g_rowsum[NROWS];
__device__ float g_cosF[NROWS];
__device__ float g_cosL[NROWS];
__device__ unsigned g_count[NRB];

// ---------------- helpers ----------------
__device__ __forceinline__ uint32_t smem_u32(const void* p) {
    uint32_t a;
    asm("{ .reg .u64 t; cvta.to.shared.u64 t, %1; cvt.u32.u64 %0, t; }" : "=r"(a) : "l"(p));
    return a;
}
__device__ __forceinline__ void mbar_init(uint32_t a, uint32_t c) {
    asm volatile("mbarrier.init.shared.b64 [%0], %1;" :: "r"(a), "r"(c) : "memory");
}
__device__ __forceinline__ void mbar_expect(uint32_t a, uint32_t tx) {
    asm volatile("mbarrier.arrive.expect_tx.shared.b64 _, [%0], %1;" :: "r"(a), "r"(tx) : "memory");
}
__device__ __forceinline__ void mbar_wait(uint32_t a, uint32_t par) {
    asm volatile(
        "{\n\t.reg .pred P;\n\t"
        "LW%=:\n\t"
        "mbarrier.try_wait.parity.acquire.cta.shared::cta.b64 P, [%0], %1, 0x989680;\n\t"
        "@P bra LD%=;\n\t"
        "bra LW%=;\n\t"
        "LD%=:\n\t}"
        :: "r"(a), "r"(par) : "memory");
}
__device__ __forceinline__ void bulk_g2s(uint32_t dst, const void* src, uint32_t bytes, uint32_t mbar) {
    asm volatile("cp.async.bulk.shared::cluster.global.mbarrier::complete_tx::bytes [%0], [%1], %2, [%3];"
                 :: "r"(dst), "l"(src), "r"(bytes), "r"(mbar) : "memory");
}
__device__ __forceinline__ void ldsm4(uint32_t r[4], uint32_t addr) {
    asm volatile("ldmatrix.sync.aligned.m8n8.x4.shared.b16 {%0,%1,%2,%3}, [%4];"
                 : "=r"(r[0]), "=r"(r[1]), "=r"(r[2]), "=r"(r[3]) : "r"(addr));
}
__device__ __forceinline__ void mma_e4m3_h(uint32_t c[2], const uint32_t a[4], const uint32_t b[2]) {
    asm volatile("mma.sync.aligned.m16n8k32.row.col.f16.e4m3.e4m3.f16 "
                 "{%0,%1}, {%2,%3,%4,%5}, {%6,%7}, {%0,%1};"
                 : "+r"(c[0]), "+r"(c[1])
                 : "r"(a[0]), "r"(a[1]), "r"(a[2]), "r"(a[3]), "r"(b[0]), "r"(b[1]));
}
__device__ __forceinline__ float ex2f(float x) {
    float y; asm("ex2.approx.ftz.f32 %0, %1;" : "=f"(y) : "f"(x)); return y;
}
__device__ __forceinline__ __half2 ex2_h2(__half2 x) {
    __half2 y;
    asm("ex2.approx.f16x2 %0, %1;" : "=r"(*(uint32_t*)&y) : "r"(*(const uint32_t*)&x));
    return y;
}
__device__ __forceinline__ uint32_t pack4_e4m3(float v0, float v1, float v2, float v3) {
    uint16_t lo, hi;
    asm("cvt.rn.satfinite.e4m3x2.f32 %0, %1, %2;" : "=h"(lo) : "f"(v1), "f"(v0));
    asm("cvt.rn.satfinite.e4m3x2.f32 %0, %1, %2;" : "=h"(hi) : "f"(v3), "f"(v2));
    return (uint32_t)lo | ((uint32_t)hi << 16);
}

// ---------------- K1: per-speaker prep -> slice-major pre-swizzled fp8 ----------------
__global__ __launch_bounds__(128) void k1_prep(const float* __restrict__ dvecs,
                                               const float* __restrict__ wp,
                                               float* out) {
    __shared__ float2 sde[MUTT*128];
    __shared__ float  sfe[MUTT];
    __shared__ float  red[4];

    const int j = blockIdx.x, tid = threadIdx.x;
    const int lane = tid & 31, wid = tid >> 5;
    const float w = *wp;
    const float sA = sqrtf(w * LOG2E);

    if (j == 0 && tid == 0) out[0] = 0.f;
    if (tid < MUTT) g_rowsum[j*MUTT + tid] = 0.f;
    if (j < NRB && tid == 64) g_count[j] = 0u;

    const int ss = tid >> 5, kc = (tid >> 2) & 7, wd = tid & 3;

    const float4* src = (const float4*)(dvecs + (size_t)j * MUTT * DDIM);
    float4 v[MUTT];
    #pragma unroll
    for (int i = 0; i < MUTT; i++) v[i] = src[i*128 + tid];

    float4 s = make_float4(0.f, 0.f, 0.f, 0.f);
    #pragma unroll
    for (int i = 0; i < MUTT; i++) { s.x += v[i].x; s.y += v[i].y; s.z += v[i].z; s.w += v[i].w; }

    float ssqp = s.x*s.x + s.y*s.y + s.z*s.z + s.w*s.w;
    #pragma unroll
    for (int o = 16; o; o >>= 1) ssqp += __shfl_xor_sync(0xffffffffu, ssqp, o);
    if (lane == 0) red[wid] = ssqp;

    #pragma unroll
    for (int i = 0; i < MUTT; i++) {
        const float dp = v[i].x*s.x + v[i].y*s.y + v[i].z*s.z + v[i].w*s.w;
        const float ep = v[i].x*v[i].x + v[i].y*v[i].y + v[i].z*v[i].z + v[i].w*v[i].w;
        sde[i*128 + tid] = make_float2(dp, ep);
    }
    __syncthreads();

    const float ssq = red[0] + red[1] + red[2] + red[3];
    const float inv_S = rsqrtf(ssq);
    const float fB = inv_S * sA;
    {
        const uint32_t off = (uint32_t)(((kc*16) ^ ((j & 7) << 4)) + wd*4);
        *(uint32_t*)(g_B8s + (size_t)ss*BSTR + (size_t)j*128 + off) =
            pack4_e4m3(s.x*fB, s.y*fB, s.z*fB, s.w*fB);
    }

    #pragma unroll
    for (int q = 0; q < 4; q++) {
        const int i = wid + 4*q;
        float2 a0 = sde[i*128 + lane];
        const float2 a1 = sde[i*128 + lane + 32];
        const float2 a2 = sde[i*128 + lane + 64];
        const float2 a3 = sde[i*128 + lane + 96];
        float dp = a0.x + a1.x + a2.x + a3.x;
        float ep = a0.y + a1.y + a2.y + a3.y;
        #pragma unroll
        for (int o = 16; o; o >>= 1) {
            dp += __shfl_xor_sync(0xffffffffu, dp, o);
            ep += __shfl_xor_sync(0xffffffffu, ep, o);
        }
        if (lane == 0) {
            const float inv_e = rsqrtf(ep);
            const int r = j * MUTT + i;
            const float cosF = dp * inv_e * inv_S;
            const float den  = fmaxf(ssq - 2.f*dp + ep, 1e-20f);
            const float cosL = (dp - ep) * inv_e * rsqrtf(den);
            g_cosF[r] = fmaxf(cosF, EPSC);
            g_cosL[r] = fmaxf(cosL, EPSC);
            sfe[i] = inv_e * sA;
        }
    }
    __syncthreads();

    #pragma unroll
    for (int i = 0; i < MUTT; i++) {
        const float fe = sfe[i];
        const int r = j*MUTT + i;
        const uint32_t off = (uint32_t)(((kc*16) ^ ((r & 7) << 4)) + wd*4);
        *(uint32_t*)(g_A8s + (size_t)ss*ASTR + (size_t)r*128 + off) =
            pack4_e4m3(v[i].x*fe, v[i].y*fe, v[i].z*fe, v[i].w*fe);
    }
}

// ---------------- K2: TMA-fed fp8 GEMM, asymmetric producer sync ----------------
// grid = 2048: rowBlock = bx>>2 (64 rows), colQ = bx&3 (512 cols)
// Warps 1-3: bar.arrive (non-blocking) after each slice; warp 0: bar.sync before TMA overwrite.
__global__ __launch_bounds__(128, 3) void k2_gemm(const float* __restrict__ wp, float* out) {
    extern __shared__ unsigned char dyns[];
    __shared__ __align__(8) uint64_t mbar[3];   // [0,1]: B double buffer, [2]: A
    __shared__ int s_last;
    const uint32_t sb = smem_u32(dyns);
    const uint32_t mb = smem_u32(mbar);

    const int tid = threadIdx.x;
    const int lane = tid & 31;
    const int warp = tid >> 5;
    const int wm = warp >> 1;     // 0..1: 32 rows
    const int wn = warp & 1;      // 0..1: 64 cols
    const int rowBlock = blockIdx.x >> 2;
    const int rowBase = rowBlock * MTR;
    const int colBase = (blockIdx.x & 3) * NCH_CTA;   // chunk units of 128
    const float w = *wp;
    const float K = w * LOG2E;
    const __half2 cKh = __float2half2_rn(K * EPSC);

    if (tid == 0) {
        #pragma unroll
        for (int i = 0; i < 3; i++) mbar_init(mb + i*8, 1);
    }
    __syncthreads();

    auto srcB = [&](int s) -> const void* {
        const int nc = colBase + (s >> 2), ksl = s & 3;
        return g_B8s + (size_t)ksl*BSTR + (size_t)nc*16384;
    };
    if (tid == 0) {
        mbar_expect(mb + 16, 4*A_SLICE);
        #pragma unroll
        for (int ss = 0; ss < 4; ss++)
            bulk_g2s(sb + (uint32_t)(ss*A_SLICE), g_A8s + (size_t)ss*ASTR + (size_t)rowBase*128,
                     A_SLICE, mb + 16);
        mbar_expect(mb + 0, 16384);
        bulk_g2s(sb + OFF_B, srcB(0), 16384u, mb + 0);
    }

    // ---- ldsm lane addresses ----
    const int grp = lane >> 3, wi = lane & 7;
    uint32_t aBase[2], aMask[2];
    const uint32_t aB16 = (uint32_t)((grp >> 1) * 16);
    #pragma unroll
    for (int mt = 0; mt < 2; mt++) {
        const int row = wm*32 + mt*16 + (grp & 1)*8 + wi;
        aBase[mt] = sb + (uint32_t)(row * 128);
        aMask[mt] = (uint32_t)((row & 7) << 4);
    }
    uint32_t bBase[4], bMask[4];
    const uint32_t bB16 = (uint32_t)((grp & 1) * 16);
    #pragma unroll
    for (int p = 0; p < 4; p++) {
        const int n = wn*64 + p*16 + (grp >> 1)*8 + wi;
        bBase[p] = sb + OFF_B + (uint32_t)(n * 128);
        bMask[p] = (uint32_t)((n & 7) << 4);
    }

    float rs[4];
    #pragma unroll
    for (int k = 0; k < 4; k++) rs[k] = 0.f;

    mbar_wait(mb + 16, 0);   // A resident

    for (int c8 = 0; c8 < NCH_CTA; c8++) {
        uint32_t acc[2][8][2];
        #pragma unroll
        for (int x = 0; x < 2; x++)
            #pragma unroll
            for (int y = 0; y < 8; y++) { acc[x][y][0] = 0u; acc[x][y][1] = 0u; }

        #pragma unroll
        for (int sc = 0; sc < 4; sc++) {
            const int s = c8*4 + sc;
            const int bfi = s & 1;

            // producer (warp 0): prove the target buffer drained, then overwrite
            if (warp == 0 && s + 1 < NSLICE) {
                if (s > 0)
                    asm volatile("bar.sync %0, 128;" :: "r"(1 + ((s - 1) & 1)) : "memory");
                if (lane == 0) {
                    const int pb = (s + 1) & 1;
                    mbar_expect(mb + pb*8, 16384);
                    bulk_g2s(sb + OFF_B + (uint32_t)(pb*16384), srcB(s + 1), 16384u, mb + pb*8);
                }
            }

            mbar_wait(mb + bfi*8, (s >> 1) & 1);

            const uint32_t aSl = (uint32_t)(sc * A_SLICE);
            const uint32_t bBuf = (uint32_t)(bfi * SLICE_B);
            #pragma unroll
            for (int kk = 0; kk < 4; kk++) {
                uint32_t afr[2][4];
                #pragma unroll
                for (int mt = 0; mt < 2; mt++)
                    ldsm4(afr[mt], aBase[mt] + aSl + (((uint32_t)(kk*32) | aB16) ^ aMask[mt]));
                uint32_t bfr[8][2];
                #pragma unroll
                for (int p = 0; p < 4; p++) {
                    uint32_t t[4];
                    ldsm4(t, bBase[p] + bBuf + (((uint32_t)(kk*32) | bB16) ^ bMask[p]));
                    bfr[2*p][0] = t[0]; bfr[2*p][1] = t[1];
                    bfr[2*p+1][0] = t[2]; bfr[2*p+1][1] = t[3];
                }
                #pragma unroll
                for (int mt = 0; mt < 2; mt++)
                    #pragma unroll
                    for (int nt = 0; nt < 8; nt++)
                        mma_e4m3_h(acc[mt][nt], afr[mt], bfr[nt]);
            }

            // consumers: non-blocking arrive (only for slices whose arrivals get consumed)
            if (warp > 0 && s < NSLICE - 2)
                asm volatile("bar.arrive %0, 128;" :: "r"(1 + (s & 1)) : "memory");
        }

        // epilogue: acc halves = K*cos ; f16 exp-sums across nt, one f32 convert per pair
        #pragma unroll
        for (int mt = 0; mt < 2; mt++) {
            __half2 h0 = ex2_h2(__hmax2(*(__half2*)&acc[mt][0][0], cKh));
            __half2 h1 = ex2_h2(__hmax2(*(__half2*)&acc[mt][0][1], cKh));
            #pragma unroll
            for (int nt = 1; nt < 8; nt++) {
                h0 = __hadd2(h0, ex2_h2(__hmax2(*(__half2*)&acc[mt][nt][0], cKh)));
                h1 = __hadd2(h1, ex2_h2(__hmax2(*(__half2*)&acc[mt][nt][1], cKh)));
            }
            const float2 f0 = __half22float2(h0);
            const float2 f1 = __half22float2(h1);
            rs[mt*2]   += f0.x + f0.y;
            rs[mt*2+1] += f1.x + f1.y;
        }
    }

    // ---- row reduction into smem (overlay on B buffers; mainloop drained) ----
    __syncthreads();
    float* rowAcc = (float*)(dyns + OFF_B);
    if (tid < MTR) rowAcc[tid] = 0.f;
    __syncthreads();

    const int g8 = lane >> 2, tt = lane & 3;
    #pragma unroll
    for (int k = 0; k < 4; k++) {
        float v = rs[k];
        v += __shfl_xor_sync(0xffffffffu, v, 1);
        v += __shfl_xor_sync(0xffffffffu, v, 2);
        if (tt == 0)
            atomicAdd(&rowAcc[wm*32 + (k >> 1)*16 + (k & 1)*8 + g8], v);
    }
    __syncthreads();

    if (tid < MTR) atomicAdd(&g_rowsum[rowBase + tid], rowAcc[tid]);
    __threadfence();
    if (tid == 0) {
        const unsigned o = atomicAdd(&g_count[rowBlock], 1u);
        s_last = (o == 3u);
    }
    __syncthreads();

    if (s_last) {
        __threadfence();
        float v = 0.f;
        if (tid < MTR) {
            const int r = rowBase + tid;
            const float fF = g_cosF[r], fL = g_cosL[r];
            v = __logf(g_rowsum[r] - ex2f(K * fF) + ex2f(K * fL)) - w * fL;
        }
        #pragma unroll
        for (int o = 16; o; o >>= 1) v += __shfl_xor_sync(0xffffffffu, v, o);
        float* red = (float*)(dyns + OFF_B + 512);
        if (lane == 0) red[warp] = v;
        __syncthreads();
        if (tid == 0) atomicAdd(out, red[0] + red[1] + red[2] + red[3]);
    }
}

// ---------------- launcher ----------------
extern "C" void kernel_launch(void* const* d_in, const int* in_sizes, int n_in,
                              void* d_out, int out_size) {
    const float* dvecs = (const float*)d_in[0];
    const float* wp    = (const float*)d_in[1];
    float* out = (float*)d_out;

    cudaFuncSetAttribute(k2_gemm, cudaFuncAttributeMaxDynamicSharedMemorySize, SMEM_K2);

    k1_prep<<<NSPK, 128>>>(dvecs, wp, out);
    k2_gemm<<<NRB*4, 128, SMEM_K2>>>(wp, out);
}

// round 15
// speedup vs baseline: 1.1112x; 1.0056x over previous
#include <cuda_runtime.h>
#include <cuda_bf16.h>
#include <cuda_fp16.h>
#include <cstdint>

#define NSPK 2048
#define MUTT 16
#define DDIM 512
#define NROWS (NSPK*MUTT)
#define EPSC 1e-6f
#define LOG2E 1.4426950408889634f

// ---- k2 tiling: 64 rows x 512 cols per CTA, 128 threads (4 warps, 32x64 each) ----
#define MTR 64
#define NCH_CTA 4               // 4 col-chunks of 128
#define NSLICE (NCH_CTA*4)      // 16 B-slices of 16KB
#define A_SLICE 8192            // 64 rows x 128 bytes per K128-slice
#define SLICE_B 16384
#define OFF_B   32768           // A resident: 4 x 8KB
#define SMEM_K2 (OFF_B + 2*SLICE_B + 512)   // 66048 -> 3 CTAs/SM, ~168 regs/thread
#define NRB (NROWS/MTR)         // 512 row blocks
#define ASTR ((size_t)NROWS*128)
#define BSTR ((size_t)NSPK*128)

// ---- scratch: K-slice-major, pre-swizzled for ldsm ----
__device__ __align__(256) uint8_t g_A8s[4*NROWS*128];
__device__ __align__(256) uint8_t g_B8s[4*NSPK*128];
__device__ float g_rowsum[NROWS];
__device__ float g_cosF[NROWS];
__device__ float g_cosL[NROWS];
__device__ unsigned g_count[NRB];

// ---------------- helpers ----------------
__device__ __forceinline__ uint32_t smem_u32(const void* p) {
    uint32_t a;
    asm("{ .reg .u64 t; cvta.to.shared.u64 t, %1; cvt.u32.u64 %0, t; }" : "=r"(a) : "l"(p));
    return a;
}
__device__ __forceinline__ void mbar_init(uint32_t a, uint32_t c) {
    asm volatile("mbarrier.init.shared.b64 [%0], %1;" :: "r"(a), "r"(c) : "memory");
}
__device__ __forceinline__ void mbar_expect(uint32_t a, uint32_t tx) {
    asm volatile("mbarrier.arrive.expect_tx.shared.b64 _, [%0], %1;" :: "r"(a), "r"(tx) : "memory");
}
__device__ __forceinline__ void mbar_wait(uint32_t a, uint32_t par) {
    asm volatile(
        "{\n\t.reg .pred P;\n\t"
        "LW%=:\n\t"
        "mbarrier.try_wait.parity.acquire.cta.shared::cta.b64 P, [%0], %1, 0x989680;\n\t"
        "@P bra LD%=;\n\t"
        "bra LW%=;\n\t"
        "LD%=:\n\t}"
        :: "r"(a), "r"(par) : "memory");
}
__device__ __forceinline__ void bulk_g2s(uint32_t dst, const void* src, uint32_t bytes, uint32_t mbar) {
    asm volatile("cp.async.bulk.shared::cluster.global.mbarrier::complete_tx::bytes [%0], [%1], %2, [%3];"
                 :: "r"(dst), "l"(src), "r"(bytes), "r"(mbar) : "memory");
}
__device__ __forceinline__ void ldsm4(uint32_t r[4], uint32_t addr) {
    asm volatile("ldmatrix.sync.aligned.m8n8.x4.shared.b16 {%0,%1,%2,%3}, [%4];"
                 : "=r"(r[0]), "=r"(r[1]), "=r"(r[2]), "=r"(r[3]) : "r"(addr));
}
__device__ __forceinline__ void mma_e4m3_h(uint32_t c[2], const uint32_t a[4], const uint32_t b[2]) {
    asm volatile("mma.sync.aligned.m16n8k32.row.col.f16.e4m3.e4m3.f16 "
                 "{%0,%1}, {%2,%3,%4,%5}, {%6,%7}, {%0,%1};"
                 : "+r"(c[0]), "+r"(c[1])
                 : "r"(a[0]), "r"(a[1]), "r"(a[2]), "r"(a[3]), "r"(b[0]), "r"(b[1]));
}
__device__ __forceinline__ float ex2f(float x) {
    float y; asm("ex2.approx.ftz.f32 %0, %1;" : "=f"(y) : "f"(x)); return y;
}
__device__ __forceinline__ __half2 ex2_h2(__half2 x) {
    __half2 y;
    asm("ex2.approx.f16x2 %0, %1;" : "=r"(*(uint32_t*)&y) : "r"(*(const uint32_t*)&x));
    return y;
}
__device__ __forceinline__ uint32_t pack4_e4m3(float v0, float v1, float v2, float v3) {
    uint16_t lo, hi;
    asm("cvt.rn.satfinite.e4m3x2.f32 %0, %1, %2;" : "=h"(lo) : "f"(v1), "f"(v0));
    asm("cvt.rn.satfinite.e4m3x2.f32 %0, %1, %2;" : "=h"(hi) : "f"(v3), "f"(v2));
    return (uint32_t)lo | ((uint32_t)hi << 16);
}

// ---------------- K1: per-speaker prep -> slice-major pre-swizzled fp8 ----------------
__global__ __launch_bounds__(128) void k1_prep(const float* __restrict__ dvecs,
                                               const float* __restrict__ wp,
                                               float* out) {
    __shared__ float2 sde[MUTT*128];
    __shared__ float  sfe[MUTT];
    __shared__ float  red[4];

    const int j = blockIdx.x, tid = threadIdx.x;
    const int lane = tid & 31, wid = tid >> 5;
    const float w = *wp;
    const float sA = sqrtf(w * LOG2E);

    if (j == 0 && tid == 0) out[0] = 0.f;
    if (tid < MUTT) g_rowsum[j*MUTT + tid] = 0.f;
    if (j < NRB && tid == 64) g_count[j] = 0u;

    const int ss = tid >> 5, kc = (tid >> 2) & 7, wd = tid & 3;

    const float4* src = (const float4*)(dvecs + (size_t)j * MUTT * DDIM);
    float4 v[MUTT];
    #pragma unroll
    for (int i = 0; i < MUTT; i++) v[i] = src[i*128 + tid];

    float4 s = make_float4(0.f, 0.f, 0.f, 0.f);
    #pragma unroll
    for (int i = 0; i < MUTT; i++) { s.x += v[i].x; s.y += v[i].y; s.z += v[i].z; s.w += v[i].w; }

    float ssqp = s.x*s.x + s.y*s.y + s.z*s.z + s.w*s.w;
    #pragma unroll
    for (int o = 16; o; o >>= 1) ssqp += __shfl_xor_sync(0xffffffffu, ssqp, o);
    if (lane == 0) red[wid] = ssqp;

    #pragma unroll
    for (int i = 0; i < MUTT; i++) {
        const float dp = v[i].x*s.x + v[i].y*s.y + v[i].z*s.z + v[i].w*s.w;
        const float ep = v[i].x*v[i].x + v[i].y*v[i].y + v[i].z*v[i].z + v[i].w*v[i].w;
        sde[i*128 + tid] = make_float2(dp, ep);
    }
    __syncthreads();

    const float ssq = red[0] + red[1] + red[2] + red[3];
    const float inv_S = rsqrtf(ssq);
    const float fB = inv_S * sA;
    {
        const uint32_t off = (uint32_t)(((kc*16) ^ ((j & 7) << 4)) + wd*4);
        *(uint32_t*)(g_B8s + (size_t)ss*BSTR + (size_t)j*128 + off) =
            pack4_e4m3(s.x*fB, s.y*fB, s.z*fB, s.w*fB);
    }

    #pragma unroll
    for (int q = 0; q < 4; q++) {
        const int i = wid + 4*q;
        float2 a0 = sde[i*128 + lane];
        const float2 a1 = sde[i*128 + lane + 32];
        const float2 a2 = sde[i*128 + lane + 64];
        const float2 a3 = sde[i*128 + lane + 96];
        float dp = a0.x + a1.x + a2.x + a3.x;
        float ep = a0.y + a1.y + a2.y + a3.y;
        #pragma unroll
        for (int o = 16; o; o >>= 1) {
            dp += __shfl_xor_sync(0xffffffffu, dp, o);
            ep += __shfl_xor_sync(0xffffffffu, ep, o);
        }
        if (lane == 0) {
            const float inv_e = rsqrtf(ep);
            const int r = j * MUTT + i;
            const float cosF = dp * inv_e * inv_S;
            const float den  = fmaxf(ssq - 2.f*dp + ep, 1e-20f);
            const float cosL = (dp - ep) * inv_e * rsqrtf(den);
            g_cosF[r] = fmaxf(cosF, EPSC);
            g_cosL[r] = fmaxf(cosL, EPSC);
            sfe[i] = inv_e * sA;
        }
    }
    __syncthreads();

    #pragma unroll
    for (int i = 0; i < MUTT; i++) {
        const float fe = sfe[i];
        const int r = j*MUTT + i;
        const uint32_t off = (uint32_t)(((kc*16) ^ ((r & 7) << 4)) + wd*4);
        *(uint32_t*)(g_A8s + (size_t)ss*ASTR + (size_t)r*128 + off) =
            pack4_e4m3(v[i].x*fe, v[i].y*fe, v[i].z*fe, v[i].w*fe);
    }
}

// ---------------- K2: TMA-fed fp8 GEMM, asymmetric sync + per-warp kk rotation ----------------
// grid = 2048: rowBlock = bx>>2 (64 rows), colQ = bx&3 (512 cols)
__global__ __launch_bounds__(128, 3) void k2_gemm(const float* __restrict__ wp, float* out) {
    extern __shared__ unsigned char dyns[];
    __shared__ __align__(8) uint64_t mbar[3];   // [0,1]: B double buffer, [2]: A
    __shared__ int s_last;
    const uint32_t sb = smem_u32(dyns);
    const uint32_t mb = smem_u32(mbar);

    const int tid = threadIdx.x;
    const int lane = tid & 31;
    const int warp = tid >> 5;
    const int wm = warp >> 1;     // 0..1: 32 rows
    const int wn = warp & 1;      // 0..1: 64 cols
    const int rowBlock = blockIdx.x >> 2;
    const int rowBase = rowBlock * MTR;
    const int colBase = (blockIdx.x & 3) * NCH_CTA;   // chunk units of 128
    const float w = *wp;
    const float K = w * LOG2E;
    const __half2 cKh = __float2half2_rn(K * EPSC);

    if (tid == 0) {
        #pragma unroll
        for (int i = 0; i < 3; i++) mbar_init(mb + i*8, 1);
    }
    __syncthreads();

    auto srcB = [&](int s) -> const void* {
        const int nc = colBase + (s >> 2), ksl = s & 3;
        return g_B8s + (size_t)ksl*BSTR + (size_t)nc*16384;
    };
    if (tid == 0) {
        mbar_expect(mb + 16, 4*A_SLICE);
        #pragma unroll
        for (int ss = 0; ss < 4; ss++)
            bulk_g2s(sb + (uint32_t)(ss*A_SLICE), g_A8s + (size_t)ss*ASTR + (size_t)rowBase*128,
                     A_SLICE, mb + 16);
        mbar_expect(mb + 0, 16384);
        bulk_g2s(sb + OFF_B, srcB(0), 16384u, mb + 0);
    }

    // ---- ldsm lane addresses ----
    const int grp = lane >> 3, wi = lane & 7;
    uint32_t aBase[2], aMask[2];
    const uint32_t aB16 = (uint32_t)((grp >> 1) * 16);
    #pragma unroll
    for (int mt = 0; mt < 2; mt++) {
        const int row = wm*32 + mt*16 + (grp & 1)*8 + wi;
        aBase[mt] = sb + (uint32_t)(row * 128);
        aMask[mt] = (uint32_t)((row & 7) << 4);
    }
    uint32_t bBase[4], bMask[4];
    const uint32_t bB16 = (uint32_t)((grp & 1) * 16);
    #pragma unroll
    for (int p = 0; p < 4; p++) {
        const int n = wn*64 + p*16 + (grp >> 1)*8 + wi;
        bBase[p] = sb + OFF_B + (uint32_t)(n * 128);
        bMask[p] = (uint32_t)((n & 7) << 4);
    }

    float rs[4];
    #pragma unroll
    for (int k = 0; k < 4; k++) rs[k] = 0.f;

    mbar_wait(mb + 16, 0);   // A resident

    for (int c8 = 0; c8 < NCH_CTA; c8++) {
        uint32_t acc[2][8][2];
        #pragma unroll
        for (int x = 0; x < 2; x++)
            #pragma unroll
            for (int y = 0; y < 8; y++) { acc[x][y][0] = 0u; acc[x][y][1] = 0u; }

        #pragma unroll
        for (int sc = 0; sc < 4; sc++) {
            const int s = c8*4 + sc;
            const int bfi = s & 1;

            // producer (warp 0): prove the target buffer drained, then overwrite
            if (warp == 0 && s + 1 < NSLICE) {
                if (s > 0)
                    asm volatile("bar.sync %0, 128;" :: "r"(1 + ((s - 1) & 1)) : "memory");
                if (lane == 0) {
                    const int pb = (s + 1) & 1;
                    mbar_expect(mb + pb*8, 16384);
                    bulk_g2s(sb + OFF_B + (uint32_t)(pb*16384), srcB(s + 1), 16384u, mb + pb*8);
                }
            }

            mbar_wait(mb + bfi*8, (s >> 1) & 1);

            const uint32_t aSl = (uint32_t)(sc * A_SLICE);
            const uint32_t bBuf = (uint32_t)(bfi * SLICE_B);
            // per-warp kk rotation: warp w starts at K-offset 32*w -> staggered LDSM bursts
            #pragma unroll
            for (int kk = 0; kk < 4; kk++) {
                const uint32_t kkr = (uint32_t)(((kk + warp) & 3) * 32);
                uint32_t afr[2][4];
                #pragma unroll
                for (int mt = 0; mt < 2; mt++)
                    ldsm4(afr[mt], aBase[mt] + aSl + ((kkr | aB16) ^ aMask[mt]));
                uint32_t bfr[8][2];
                #pragma unroll
                for (int p = 0; p < 4; p++) {
                    uint32_t t[4];
                    ldsm4(t, bBase[p] + bBuf + ((kkr | bB16) ^ bMask[p]));
                    bfr[2*p][0] = t[0]; bfr[2*p][1] = t[1];
                    bfr[2*p+1][0] = t[2]; bfr[2*p+1][1] = t[3];
                }
                #pragma unroll
                for (int mt = 0; mt < 2; mt++)
                    #pragma unroll
                    for (int nt = 0; nt < 8; nt++)
                        mma_e4m3_h(acc[mt][nt], afr[mt], bfr[nt]);
            }

            // consumers: non-blocking arrive (only for slices whose arrivals get consumed)
            if (warp > 0 && s < NSLICE - 2)
                asm volatile("bar.arrive %0, 128;" :: "r"(1 + (s & 1)) : "memory");
        }

        // epilogue: acc halves = K*cos ; f16 exp-sums across nt, one f32 convert per pair
        #pragma unroll
        for (int mt = 0; mt < 2; mt++) {
            __half2 h0 = ex2_h2(__hmax2(*(__half2*)&acc[mt][0][0], cKh));
            __half2 h1 = ex2_h2(__hmax2(*(__half2*)&acc[mt][0][1], cKh));
            #pragma unroll
            for (int nt = 1; nt < 8; nt++) {
                h0 = __hadd2(h0, ex2_h2(__hmax2(*(__half2*)&acc[mt][nt][0], cKh)));
                h1 = __hadd2(h1, ex2_h2(__hmax2(*(__half2*)&acc[mt][nt][1], cKh)));
            }
            const float2 f0 = __half22float2(h0);
            const float2 f1 = __half22float2(h1);
            rs[mt*2]   += f0.x + f0.y;
            rs[mt*2+1] += f1.x + f1.y;
        }
    }

    // ---- row reduction into smem (overlay on B buffers; mainloop drained) ----
    __syncthreads();
    float* rowAcc = (float*)(dyns + OFF_B);
    if (tid < MTR) rowAcc[tid] = 0.f;
    __syncthreads();

    const int g8 = lane >> 2, tt = lane & 3;
    #pragma unroll
    for (int k = 0; k < 4; k++) {
        float v = rs[k];
        v += __shfl_xor_sync(0xffffffffu, v, 1);
        v += __shfl_xor_sync(0xffffffffu, v, 2);
        if (tt == 0)
            atomicAdd(&rowAcc[wm*32 + (k >> 1)*16 + (k & 1)*8 + g8], v);
    }
    __syncthreads();

    if (tid < MTR) atomicAdd(&g_rowsum[rowBase + tid], rowAcc[tid]);
    __threadfence();
    if (tid == 0) {
        const unsigned o = atomicAdd(&g_count[rowBlock], 1u);
        s_last = (o == 3u);
    }
    __syncthreads();

    if (s_last) {
        __threadfence();
        float v = 0.f;
        if (tid < MTR) {
            const int r = rowBase + tid;
            const float fF = g_cosF[r], fL = g_cosL[r];
            v = __logf(g_rowsum[r] - ex2f(K * fF) + ex2f(K * fL)) - w * fL;
        }
        #pragma unroll
        for (int o = 16; o; o >>= 1) v += __shfl_xor_sync(0xffffffffu, v, o);
        float* red = (float*)(dyns + OFF_B + 512);
        if (lane == 0) red[warp] = v;
        __syncthreads();
        if (tid == 0) atomicAdd(out, red[0] + red[1] + red[2] + red[3]);
    }
}

// ---------------- launcher ----------------
extern "C" void kernel_launch(void* const* d_in, const int* in_sizes, int n_in,
                              void* d_out, int out_size) {
    const float* dvecs = (const float*)d_in[0];
    const float* wp    = (const float*)d_in[1];
    float* out = (float*)d_out;

    cudaFuncSetAttribute(k2_gemm, cudaFuncAttributeMaxDynamicSharedMemorySize, SMEM_K2);

    k1_prep<<<NSPK, 128>>>(dvecs, wp, out);
    k2_gemm<<<NRB*4, 128, SMEM_K2>>>(wp, out);
}